// round 1
// baseline (speedup 1.0000x reference)
#include <cuda_runtime.h>
#include <cstddef>

#define HW 128
#define NPIX 16384
#define CHN 128
#define BATCH 4
#define NSLICE 64

// ---------------- scratch (device globals; no allocation allowed) -------------
__device__ float g_buf1[BATCH * CHN * NPIX];          // conv1 output (after leaky)
__device__ float g_feat[BATCH * CHN * NPIX];          // 1x1 partial, then feat, then normalized V
__device__ float g_gpart[NSLICE * BATCH * CHN * CHN]; // split-K partials for G
__device__ float g_G[BATCH * CHN * CHN];
__device__ float g_Ginv[BATCH * CHN * CHN];
__device__ float g_work[BATCH * CHN * CHN];           // GJ working copy
__device__ float g_tpart[NSLICE * BATCH * CHN * 64];  // split-K partials for t
__device__ float g_t2[BATCH * CHN * 64];
__device__ float g_s[BATCH * CHN];                    // reciprocal L1 row norms

__device__ __forceinline__ float leakyf(float v) { return v >= 0.f ? v : 0.2f * v; }

// ---------------- conv 3x3 (direct, tiled) -----------------------------------
// block: 256 threads = 16 oc * 16 rows; tile = 16 oc x 16x16 spatial
// FIRST: input = cat(x1,x2), also computes 1x1 conv partial into g_feat
// !FIRST: input = g_buf1, adds leaky(conv) onto g_feat (completing feat)
template <bool FIRST>
__global__ __launch_bounds__(256, 2) void conv3x3_kernel(
    const float* __restrict__ x1, const float* __restrict__ x2,
    const float* __restrict__ w, const float* __restrict__ bias,
    const float* __restrict__ wi, const float* __restrict__ bi)
{
    __shared__ float sIn[8][18][19];
    __shared__ float sW[16][8][9];
    __shared__ float sWi[16][8];

    const int tid = threadIdx.x;
    const int b = blockIdx.z >> 3;
    const int ocT = blockIdx.z & 7;
    const int r0 = blockIdx.y * 16, c0 = blockIdx.x * 16;
    const int ocl = tid >> 4, row = tid & 15;
    const int oc = ocT * 16 + ocl;

    float acc[16], acc2[16];
#pragma unroll
    for (int i = 0; i < 16; i++) { acc[i] = 0.f; acc2[i] = 0.f; }

    for (int cc = 0; cc < 16; cc++) {  // 16 chunks of 8 input channels
        // ---- stage input tile (8 ch x 18x18, zero-padded halo) ----
        for (int idx = tid; idx < 8 * 18 * 18; idx += 256) {
            int icl = idx / 324, rem = idx % 324;
            int r = rem / 18, c = rem % 18;
            int gr = r0 - 1 + r, gc = c0 - 1 + c;
            float v = 0.f;
            if ((unsigned)gr < 128u && (unsigned)gc < 128u) {
                int ic = cc * 8 + icl;
                const float* p;
                if (FIRST)
                    p = (ic < 64) ? x1 + (size_t)(b * 64 + ic) * NPIX
                                  : x2 + (size_t)(b * 64 + ic - 64) * NPIX;
                else
                    p = g_buf1 + (size_t)(b * CHN + ic) * NPIX;
                v = p[gr * 128 + gc];
            }
            sIn[icl][r][c] = v;
        }
        // ---- stage weights ----
        for (int idx = tid; idx < 16 * 8 * 9; idx += 256) {
            int o = idx / 72, rem = idx % 72;
            int icl = rem / 9, k = rem % 9;
            sW[o][icl][k] = w[(size_t)(ocT * 16 + o) * CHN * 9 + (cc * 8 + icl) * 9 + k];
        }
        if (FIRST && tid < 128) {
            int o = tid >> 3, icl = tid & 7;
            sWi[o][icl] = wi[(size_t)(ocT * 16 + o) * CHN + cc * 8 + icl];
        }
        __syncthreads();

        // ---- compute ----
#pragma unroll
        for (int icl = 0; icl < 8; icl++) {
            float wr[9];
#pragma unroll
            for (int k = 0; k < 9; k++) wr[k] = sW[ocl][icl][k];
            float wiv = FIRST ? sWi[ocl][icl] : 0.f;
#pragma unroll
            for (int dr = 0; dr < 3; dr++) {
                float in[18];
#pragma unroll
                for (int c = 0; c < 18; c++) in[c] = sIn[icl][row + dr][c];
#pragma unroll
                for (int dc = 0; dc < 3; dc++) {
                    float wv = wr[dr * 3 + dc];
#pragma unroll
                    for (int px = 0; px < 16; px++) acc[px] += in[px + dc] * wv;
                }
                if (FIRST && dr == 1) {
#pragma unroll
                    for (int px = 0; px < 16; px++) acc2[px] += in[px + 1] * wiv;
                }
            }
        }
        __syncthreads();
    }

    float bv = bias[oc];
    size_t base = ((size_t)(b * CHN + oc) * 128 + (r0 + row)) * 128 + c0;
    if (FIRST) {
        float biv = bi[oc];
#pragma unroll
        for (int q = 0; q < 4; q++) {
            float4 v, u;
            v.x = leakyf(acc[q * 4 + 0] + bv); v.y = leakyf(acc[q * 4 + 1] + bv);
            v.z = leakyf(acc[q * 4 + 2] + bv); v.w = leakyf(acc[q * 4 + 3] + bv);
            u.x = acc2[q * 4 + 0] + biv; u.y = acc2[q * 4 + 1] + biv;
            u.z = acc2[q * 4 + 2] + biv; u.w = acc2[q * 4 + 3] + biv;
            *(float4*)(g_buf1 + base + q * 4) = v;
            *(float4*)(g_feat + base + q * 4) = u;
        }
    } else {
#pragma unroll
        for (int q = 0; q < 4; q++) {
            float4 prev = *(const float4*)(g_feat + base + q * 4);
            float4 v;
            v.x = prev.x + leakyf(acc[q * 4 + 0] + bv);
            v.y = prev.y + leakyf(acc[q * 4 + 1] + bv);
            v.z = prev.z + leakyf(acc[q * 4 + 2] + bv);
            v.w = prev.w + leakyf(acc[q * 4 + 3] + bv);
            *(float4*)(g_feat + base + q * 4) = v;
        }
    }
}

// ---------------- L1 row sums -> reciprocal scales ----------------------------
__global__ void rowsum_kernel()
{
    int bc = blockIdx.x;  // 0..511
    const float* p = g_feat + (size_t)bc * NPIX;
    float s = 0.f;
    for (int i = threadIdx.x; i < NPIX; i += 256) s += fabsf(p[i]);
    __shared__ float red[256];
    red[threadIdx.x] = s;
    __syncthreads();
    for (int st = 128; st > 0; st >>= 1) {
        if (threadIdx.x < st) red[threadIdx.x] += red[threadIdx.x + st];
        __syncthreads();
    }
    if (threadIdx.x == 0) g_s[bc] = 1.0f / (1e-6f + red[0]);
}

__global__ void scale_kernel()
{
    const int total = BATCH * CHN * NPIX;
    for (int idx = blockIdx.x * blockDim.x + threadIdx.x; idx < total;
         idx += gridDim.x * blockDim.x)
        g_feat[idx] *= g_s[idx >> 14];
}

// ---------------- G = V V^T, split-K partials --------------------------------
__global__ __launch_bounds__(256) void gemmG_kernel()
{
    const int slice = blockIdx.x, b = blockIdx.y;
    const int k0 = slice * 256;
    __shared__ float sV[128][33];  // [c][k]
    const int tid = threadIdx.x, tx = tid & 15, ty = tid >> 4;
    float acc[8][8];
#pragma unroll
    for (int i = 0; i < 8; i++)
#pragma unroll
        for (int j = 0; j < 8; j++) acc[i][j] = 0.f;

    const float* base = g_feat + (size_t)b * CHN * NPIX;
    for (int kt = 0; kt < 8; kt++) {
        int kk0 = k0 + kt * 32;
        for (int idx = tid; idx < 128 * 32; idx += 256) {
            int c = idx >> 5, k = idx & 31;
            sV[c][k] = base[(size_t)c * NPIX + kk0 + k];
        }
        __syncthreads();
#pragma unroll 4
        for (int k = 0; k < 32; k++) {
            float a[8], bb[8];
#pragma unroll
            for (int i = 0; i < 8; i++) a[i] = sV[ty * 8 + i][k];
#pragma unroll
            for (int j = 0; j < 8; j++) bb[j] = sV[tx * 8 + j][k];
#pragma unroll
            for (int i = 0; i < 8; i++)
#pragma unroll
                for (int j = 0; j < 8; j++) acc[i][j] += a[i] * bb[j];
        }
        __syncthreads();
    }
    float* out = g_gpart + ((size_t)slice * BATCH + b) * CHN * CHN;
#pragma unroll
    for (int i = 0; i < 8; i++)
#pragma unroll
        for (int j = 0; j < 8; j++)
            out[(ty * 8 + i) * 128 + tx * 8 + j] = acc[i][j];
}

__global__ void reduceG_kernel()
{
    int o = blockIdx.x * 256 + threadIdx.x;  // 65536 outputs
    float s = 0.f;
    for (int sl = 0; sl < NSLICE; sl++)
        s += g_gpart[(size_t)sl * (BATCH * CHN * CHN) + o];
    g_G[o] = s;
}

// ---------------- inverse via Gauss-Jordan (SPD, no pivoting) ----------------
// One block per batch; 64KB working set stays L1/L2-hot.
__global__ __launch_bounds__(256) void inv_kernel()
{
    const int b = blockIdx.x, tid = threadIdx.x;
    float* A = g_work + b * CHN * CHN;
    float* Bi = g_Ginv + b * CHN * CHN;
    for (int i = tid; i < CHN * CHN; i += 256) {
        A[i] = g_G[b * CHN * CHN + i];
        Bi[i] = ((i >> 7) == (i & 127)) ? 1.f : 0.f;
    }
    __shared__ float fcol[128];
    __shared__ float pinv_s;
    __syncthreads();

    float* R = (tid < 128) ? A : Bi;
    const int jj = tid & 127;
    for (int p = 0; p < 128; p++) {
        if (tid == 0) pinv_s = 1.0f / A[p * 128 + p];
        __syncthreads();
        float prow = R[p * 128 + jj] * pinv_s;
        R[p * 128 + jj] = prow;
        if (tid < 128) fcol[tid] = A[tid * 128 + p];  // col p untouched by row-p scale (except diag, unused)
        __syncthreads();
#pragma unroll 4
        for (int i = 0; i < 128; i++) {
            if (i == p) continue;
            R[i * 128 + jj] -= fcol[i] * prow;
        }
        __syncthreads();
    }
}

// ---------------- t = V @ x1^T, split-K partials -----------------------------
__global__ __launch_bounds__(256) void gemmT_kernel(const float* __restrict__ x1)
{
    const int slice = blockIdx.x, b = blockIdx.y;
    const int k0 = slice * 256;
    __shared__ float sV[128][33];
    __shared__ float sX[64][33];
    const int tid = threadIdx.x, tx = tid & 15, ty = tid >> 4;
    float acc[8][4];
#pragma unroll
    for (int i = 0; i < 8; i++)
#pragma unroll
        for (int j = 0; j < 4; j++) acc[i][j] = 0.f;

    const float* vbase = g_feat + (size_t)b * CHN * NPIX;
    const float* xbase = x1 + (size_t)b * 64 * NPIX;
    for (int kt = 0; kt < 8; kt++) {
        int kk0 = k0 + kt * 32;
        for (int idx = tid; idx < 128 * 32; idx += 256) {
            int c = idx >> 5, k = idx & 31;
            sV[c][k] = vbase[(size_t)c * NPIX + kk0 + k];
        }
        for (int idx = tid; idx < 64 * 32; idx += 256) {
            int m = idx >> 5, k = idx & 31;
            sX[m][k] = xbase[(size_t)m * NPIX + kk0 + k];
        }
        __syncthreads();
#pragma unroll 4
        for (int k = 0; k < 32; k++) {
            float a[8], xb[4];
#pragma unroll
            for (int i = 0; i < 8; i++) a[i] = sV[ty * 8 + i][k];
#pragma unroll
            for (int j = 0; j < 4; j++) xb[j] = sX[tx * 4 + j][k];
#pragma unroll
            for (int i = 0; i < 8; i++)
#pragma unroll
                for (int j = 0; j < 4; j++) acc[i][j] += a[i] * xb[j];
        }
        __syncthreads();
    }
    float* out = g_tpart + ((size_t)slice * BATCH + b) * CHN * 64;
#pragma unroll
    for (int i = 0; i < 8; i++)
#pragma unroll
        for (int j = 0; j < 4; j++)
            out[(ty * 8 + i) * 64 + tx * 4 + j] = acc[i][j];
}

// reduce t partials + apply Ginv: t2 = Ginv @ t  (per batch block)
__global__ __launch_bounds__(256) void t2_kernel()
{
    __shared__ float ts[CHN * 64];
    const int b = blockIdx.x, tid = threadIdx.x;
    for (int e = tid; e < CHN * 64; e += 256) {
        float s = 0.f;
        for (int sl = 0; sl < NSLICE; sl++)
            s += g_tpart[((size_t)sl * BATCH + b) * CHN * 64 + e];
        ts[e] = s;
    }
    __syncthreads();
    const float* Gi = g_Ginv + b * CHN * CHN;
    for (int o = tid; o < CHN * 64; o += 256) {
        int c = o >> 6, m = o & 63;
        float s = 0.f;
#pragma unroll 8
        for (int d = 0; d < 128; d++) s += Gi[c * 128 + d] * ts[d * 64 + m];
        g_t2[b * CHN * 64 + o] = s;
    }
}

// ---------------- bridge[b][m][n] = sum_c V[c][n] * t2[c][m] -----------------
__global__ __launch_bounds__(256) void proj_kernel(float* __restrict__ out)
{
    __shared__ float st2[CHN * 64];
    __shared__ float sV[16][128];
    const int b = blockIdx.y;
    const int n0 = blockIdx.x * 128;
    const int tid = threadIdx.x, tx = tid & 31, ty = tid >> 5;
    for (int e = tid; e < CHN * 64; e += 256) st2[e] = g_t2[b * CHN * 64 + e];

    float acc[8][4];
#pragma unroll
    for (int i = 0; i < 8; i++)
#pragma unroll
        for (int j = 0; j < 4; j++) acc[i][j] = 0.f;

    const float* Vb = g_feat + (size_t)b * CHN * NPIX;
    for (int cc = 0; cc < 8; cc++) {
        __syncthreads();
        for (int idx = tid; idx < 16 * 128; idx += 256) {
            int k = idx >> 7, px = idx & 127;
            sV[k][px] = Vb[(size_t)(cc * 16 + k) * NPIX + n0 + px];
        }
        __syncthreads();
#pragma unroll 4
        for (int k = 0; k < 16; k++) {
            int c = cc * 16 + k;
            float4 v4 = *(const float4*)&sV[k][tx * 4];
            float vv[4] = {v4.x, v4.y, v4.z, v4.w};
            float tm[8];
#pragma unroll
            for (int i = 0; i < 8; i++) tm[i] = st2[c * 64 + ty * 8 + i];
#pragma unroll
            for (int i = 0; i < 8; i++)
#pragma unroll
                for (int j = 0; j < 4; j++) acc[i][j] += tm[i] * vv[j];
        }
    }
#pragma unroll
    for (int i = 0; i < 8; i++) {
        int m = ty * 8 + i;
        float4 v;
        v.x = acc[i][0]; v.y = acc[i][1]; v.z = acc[i][2]; v.w = acc[i][3];
        *(float4*)&out[((size_t)b * 64 + m) * NPIX + n0 + tx * 4] = v;
    }
}

// ---------------- launch -----------------------------------------------------
extern "C" void kernel_launch(void* const* d_in, const int* in_sizes, int n_in,
                              void* d_out, int out_size)
{
    const float* x1 = (const float*)d_in[0];
    const float* x2 = (const float*)d_in[1];
    const float* w1 = (const float*)d_in[2];
    const float* b1 = (const float*)d_in[3];
    const float* w2 = (const float*)d_in[4];
    const float* b2 = (const float*)d_in[5];
    const float* wi = (const float*)d_in[6];
    const float* bi = (const float*)d_in[7];
    float* out = (float*)d_out;

    dim3 cgrid(8, 8, 32);
    conv3x3_kernel<true><<<cgrid, 256>>>(x1, x2, w1, b1, wi, bi);
    conv3x3_kernel<false><<<cgrid, 256>>>(x1, x2, w2, b2, nullptr, nullptr);
    rowsum_kernel<<<512, 256>>>();
    scale_kernel<<<4096, 256>>>();
    gemmG_kernel<<<dim3(NSLICE, BATCH), 256>>>();
    reduceG_kernel<<<256, 256>>>();
    inv_kernel<<<BATCH, 256>>>();
    gemmT_kernel<<<dim3(NSLICE, BATCH), 256>>>(x1);
    t2_kernel<<<BATCH, 256>>>();
    proj_kernel<<<dim3(128, BATCH), 256>>>(out);
}

// round 2
// speedup vs baseline: 2.3613x; 2.3613x over previous
#include <cuda_runtime.h>
#include <cstdint>
#include <cstddef>

#define NPIX 16384
#define CHN 128
#define BATCH 4
#define NSLICE 64

// ---------------- scratch (device globals; no allocation allowed) -------------
__device__ float g_buf1[BATCH * CHN * NPIX];          // conv1 output (after leaky)
__device__ float g_feat[BATCH * CHN * NPIX];          // feat, then normalized V
__device__ float g_gpart[NSLICE * BATCH * CHN * CHN]; // split-K partials for G
__device__ float g_G[BATCH * CHN * CHN];
__device__ float g_tpart[NSLICE * BATCH * CHN * 64];  // split-K partials for t
__device__ float g_t2[BATCH * CHN * 64];
// repacked tf32 weights, per-lane fragment order
__device__ uint32_t g_wr1[16 * 9 * 8 * 32 * 4];
__device__ uint32_t g_wr2[16 * 9 * 8 * 32 * 4];
__device__ uint32_t g_wir[16 * 8 * 32 * 4];

__device__ __forceinline__ float leakyf(float v) { return v >= 0.f ? v : 0.2f * v; }

__device__ __forceinline__ uint32_t f2tf32(float f) {
    uint32_t o;
    asm("cvt.rna.tf32.f32 %0, %1;" : "=r"(o) : "f"(f));
    return o;
}

__device__ __forceinline__ void mma_tf32(float* acc, const uint4& a, uint32_t b0, uint32_t b1) {
    asm volatile(
        "mma.sync.aligned.m16n8k8.row.col.f32.tf32.tf32.f32 "
        "{%0,%1,%2,%3}, {%4,%5,%6,%7}, {%8,%9}, {%0,%1,%2,%3};"
        : "+f"(acc[0]), "+f"(acc[1]), "+f"(acc[2]), "+f"(acc[3])
        : "r"(a.x), "r"(a.y), "r"(a.z), "r"(a.w), "r"(b0), "r"(b1));
}

// ---------------- weight repack (fp32 -> tf32, fragment order) ---------------
// out[chunk][tap][ocgrp][lane][4]: a0=W[oc][ic], a1=W[oc+8][ic], a2=W[oc][ic+4], a3=W[oc+8][ic+4]
__global__ void repack_w3_kernel(const float* __restrict__ w, uint32_t* __restrict__ out)
{
    int idx = blockIdx.x * 256 + threadIdx.x;
    if (idx >= 16 * 9 * 8 * 32) return;
    int lane = idx & 31;
    int t2 = idx >> 5;
    int ocg = t2 & 7;
    int t3 = t2 >> 3;
    int tap = t3 % 9;
    int chunk = t3 / 9;
    int oc = ocg * 16 + (lane >> 2);
    int ic = chunk * 8 + (lane & 3);
    uint32_t* o = out + (size_t)idx * 4;
    o[0] = f2tf32(w[((size_t)oc * CHN + ic) * 9 + tap]);
    o[1] = f2tf32(w[((size_t)(oc + 8) * CHN + ic) * 9 + tap]);
    o[2] = f2tf32(w[((size_t)oc * CHN + ic + 4) * 9 + tap]);
    o[3] = f2tf32(w[((size_t)(oc + 8) * CHN + ic + 4) * 9 + tap]);
}

__global__ void repack_wi_kernel(const float* __restrict__ wi, uint32_t* __restrict__ out)
{
    int idx = blockIdx.x * 256 + threadIdx.x;
    if (idx >= 16 * 8 * 32) return;
    int lane = idx & 31;
    int ocg = (idx >> 5) & 7;
    int chunk = idx >> 8;
    int oc = ocg * 16 + (lane >> 2);
    int ic = chunk * 8 + (lane & 3);
    uint32_t* o = out + (size_t)idx * 4;
    o[0] = f2tf32(wi[(size_t)oc * CHN + ic]);
    o[1] = f2tf32(wi[(size_t)(oc + 8) * CHN + ic]);
    o[2] = f2tf32(wi[(size_t)oc * CHN + ic + 4]);
    o[3] = f2tf32(wi[(size_t)(oc + 8) * CHN + ic + 4]);
}

// ---------------- conv 3x3 via tf32 mma (implicit GEMM) ----------------------
// block = 256 thr (8 warps), tile: M=128 oc, N=128 px (8 rows x 16 cols)
// warpM = wid&3 (32 oc), warpN = wid>>2 (4 image rows of 16 px)
// FIRST: input cat(x1,x2); also 1x1 conv (tap dr=1,dc=1 with wi) into acc2
template <bool FIRST>
__global__ __launch_bounds__(256, 1) void conv_mma_kernel(
    const float* __restrict__ x1, const float* __restrict__ x2,
    const float* __restrict__ bias, const float* __restrict__ bi)
{
    __shared__ float sIn[10 * 8 * 24];      // [row 10][ic 8][px 24 (18 used)]
    __shared__ uint4 sW[9 * 8 * 32];        // [tap][ocgrp][lane] fragment float4
    __shared__ uint4 sWi[8 * 32];

    const int tid = threadIdx.x;
    const int lane = tid & 31;
    const int wid = tid >> 5;
    const int warpM = wid & 3;
    const int warpN = wid >> 2;
    const int lq = lane >> 2;   // 0..7
    const int lr = lane & 3;    // 0..3
    const int b = blockIdx.z;
    const int r0 = blockIdx.y * 8;
    const int c0 = blockIdx.x * 16;

    float acc[2][8][4];
    float acc2[2][8][4];
#pragma unroll
    for (int m = 0; m < 2; m++)
#pragma unroll
        for (int j = 0; j < 8; j++)
#pragma unroll
            for (int e = 0; e < 4; e++) { acc[m][j][e] = 0.f; if (FIRST) acc2[m][j][e] = 0.f; }

    const uint4* wsrc = (const uint4*)(FIRST ? g_wr1 : g_wr2);
    const uint4* wisrc = (const uint4*)g_wir;

    for (int cc = 0; cc < 16; cc++) {
        // ---- stage input tile: 8 ic x 10 rows x 18 px (zero-padded halo) ----
        for (int idx = tid; idx < 8 * 10 * 18; idx += 256) {
            int r = idx / 144;
            int rem = idx - r * 144;
            int ic = rem / 18;
            int px = rem - ic * 18;
            int gr = r0 - 1 + r, gc = c0 - 1 + px;
            float v = 0.f;
            if ((unsigned)gr < 128u && (unsigned)gc < 128u) {
                int icg = cc * 8 + ic;
                const float* p;
                if (FIRST)
                    p = (icg < 64) ? x1 + (size_t)(b * 64 + icg) * NPIX
                                   : x2 + (size_t)(b * 64 + icg - 64) * NPIX;
                else
                    p = g_buf1 + (size_t)(b * CHN + icg) * NPIX;
                v = p[gr * 128 + gc];
            }
            sIn[(r * 8 + ic) * 24 + px] = __uint_as_float(f2tf32(v));
        }
        // ---- stage weight slab (contiguous) ----
        {
            const uint4* src = wsrc + (size_t)cc * (9 * 8 * 32);
            for (int i = tid; i < 9 * 8 * 32; i += 256) sW[i] = src[i];
            if (FIRST && tid < 256) sWi[tid] = wisrc[(size_t)cc * 256 + tid];
        }
        __syncthreads();

        // ---- compute: 9 taps ----
#pragma unroll
        for (int tap = 0; tap < 9; tap++) {
            const int dr = tap / 3, dc = tap % 3;
            uint4 afr0 = sW[(tap * 8 + warpM * 2 + 0) * 32 + lane];
            uint4 afr1 = sW[(tap * 8 + warpM * 2 + 1) * 32 + lane];
#pragma unroll
            for (int j = 0; j < 8; j++) {
                int row = warpN * 4 + (j >> 1) + dr;
                int pxb = (j & 1) * 8 + lq + dc;
                uint32_t b0 = __float_as_uint(sIn[(row * 8 + lr) * 24 + pxb]);
                uint32_t b1 = __float_as_uint(sIn[(row * 8 + lr + 4) * 24 + pxb]);
                mma_tf32(acc[0][j], afr0, b0, b1);
                mma_tf32(acc[1][j], afr1, b0, b1);
            }
        }
        if (FIRST) {  // 1x1 conv tap (center pixel)
            uint4 wf0 = sWi[(warpM * 2 + 0) * 32 + lane];
            uint4 wf1 = sWi[(warpM * 2 + 1) * 32 + lane];
#pragma unroll
            for (int j = 0; j < 8; j++) {
                int row = warpN * 4 + (j >> 1) + 1;
                int pxb = (j & 1) * 8 + lq + 1;
                uint32_t b0 = __float_as_uint(sIn[(row * 8 + lr) * 24 + pxb]);
                uint32_t b1 = __float_as_uint(sIn[(row * 8 + lr + 4) * 24 + pxb]);
                mma_tf32(acc2[0][j], wf0, b0, b1);
                mma_tf32(acc2[1][j], wf1, b0, b1);
            }
        }
        __syncthreads();
    }

    // ---- epilogue ----
#pragma unroll
    for (int m = 0; m < 2; m++) {
        int oc = warpM * 32 + m * 16 + lq;
        float bv0 = bias[oc], bv1 = bias[oc + 8];
        float bi0 = 0.f, bi1 = 0.f;
        if (FIRST) { bi0 = bi[oc]; bi1 = bi[oc + 8]; }
#pragma unroll
        for (int j = 0; j < 8; j++) {
            int irow = r0 + warpN * 4 + (j >> 1);
            int icol = c0 + (j & 1) * 8 + lr * 2;
            size_t base0 = ((size_t)(b * CHN + oc) * 128 + irow) * 128 + icol;
            size_t base1 = base0 + (size_t)8 * NPIX;
            if (FIRST) {
                float2 v0, v1, u0, u1;
                v0.x = leakyf(acc[m][j][0] + bv0); v0.y = leakyf(acc[m][j][1] + bv0);
                v1.x = leakyf(acc[m][j][2] + bv1); v1.y = leakyf(acc[m][j][3] + bv1);
                u0.x = acc2[m][j][0] + bi0; u0.y = acc2[m][j][1] + bi0;
                u1.x = acc2[m][j][2] + bi1; u1.y = acc2[m][j][3] + bi1;
                *(float2*)(g_buf1 + base0) = v0;
                *(float2*)(g_buf1 + base1) = v1;
                *(float2*)(g_feat + base0) = u0;
                *(float2*)(g_feat + base1) = u1;
            } else {
                float2 p0 = *(const float2*)(g_feat + base0);
                float2 p1 = *(const float2*)(g_feat + base1);
                p0.x += leakyf(acc[m][j][0] + bv0); p0.y += leakyf(acc[m][j][1] + bv0);
                p1.x += leakyf(acc[m][j][2] + bv1); p1.y += leakyf(acc[m][j][3] + bv1);
                *(float2*)(g_feat + base0) = p0;
                *(float2*)(g_feat + base1) = p1;
            }
        }
    }
}

// ---------------- L1 row sums + in-place scale --------------------------------
__global__ void rowsum_scale_kernel()
{
    int bc = blockIdx.x;  // 0..511
    float* p = g_feat + (size_t)bc * NPIX;
    float s = 0.f;
    for (int i = threadIdx.x; i < NPIX; i += 256) s += fabsf(p[i]);
    __shared__ float red[256];
    red[threadIdx.x] = s;
    __syncthreads();
    for (int st = 128; st > 0; st >>= 1) {
        if (threadIdx.x < st) red[threadIdx.x] += red[threadIdx.x + st];
        __syncthreads();
    }
    float inv = 1.0f / (1e-6f + red[0]);
    for (int i = threadIdx.x; i < NPIX; i += 256) p[i] *= inv;
}

// ---------------- G = V V^T, split-K partials --------------------------------
__global__ __launch_bounds__(256) void gemmG_kernel()
{
    const int slice = blockIdx.x, b = blockIdx.y;
    const int k0 = slice * 256;
    __shared__ float sV[128][33];
    const int tid = threadIdx.x, tx = tid & 15, ty = tid >> 4;
    float acc[8][8];
#pragma unroll
    for (int i = 0; i < 8; i++)
#pragma unroll
        for (int j = 0; j < 8; j++) acc[i][j] = 0.f;

    const float* base = g_feat + (size_t)b * CHN * NPIX;
    for (int kt = 0; kt < 8; kt++) {
        int kk0 = k0 + kt * 32;
        for (int idx = tid; idx < 128 * 32; idx += 256) {
            int c = idx >> 5, k = idx & 31;
            sV[c][k] = base[(size_t)c * NPIX + kk0 + k];
        }
        __syncthreads();
#pragma unroll 4
        for (int k = 0; k < 32; k++) {
            float a[8], bb[8];
#pragma unroll
            for (int i = 0; i < 8; i++) a[i] = sV[ty * 8 + i][k];
#pragma unroll
            for (int j = 0; j < 8; j++) bb[j] = sV[tx * 8 + j][k];
#pragma unroll
            for (int i = 0; i < 8; i++)
#pragma unroll
                for (int j = 0; j < 8; j++) acc[i][j] += a[i] * bb[j];
        }
        __syncthreads();
    }
    float* out = g_gpart + ((size_t)slice * BATCH + b) * CHN * CHN;
#pragma unroll
    for (int i = 0; i < 8; i++)
#pragma unroll
        for (int j = 0; j < 8; j++)
            out[(ty * 8 + i) * 128 + tx * 8 + j] = acc[i][j];
}

__global__ void reduceG_kernel()
{
    int o = blockIdx.x * 256 + threadIdx.x;
    float s = 0.f;
    for (int sl = 0; sl < NSLICE; sl++)
        s += g_gpart[(size_t)sl * (BATCH * CHN * CHN) + o];
    g_G[o] = s;
}

// ---------------- t = V @ x1^T, split-K partials -----------------------------
__global__ __launch_bounds__(256) void gemmT_kernel(const float* __restrict__ x1)
{
    const int slice = blockIdx.x, b = blockIdx.y;
    const int k0 = slice * 256;
    __shared__ float sV[128][33];
    __shared__ float sX[64][33];
    const int tid = threadIdx.x, tx = tid & 15, ty = tid >> 4;
    float acc[8][4];
#pragma unroll
    for (int i = 0; i < 8; i++)
#pragma unroll
        for (int j = 0; j < 4; j++) acc[i][j] = 0.f;

    const float* vbase = g_feat + (size_t)b * CHN * NPIX;
    const float* xbase = x1 + (size_t)b * 64 * NPIX;
    for (int kt = 0; kt < 8; kt++) {
        int kk0 = k0 + kt * 32;
        for (int idx = tid; idx < 128 * 32; idx += 256) {
            int c = idx >> 5, k = idx & 31;
            sV[c][k] = vbase[(size_t)c * NPIX + kk0 + k];
        }
        for (int idx = tid; idx < 64 * 32; idx += 256) {
            int m = idx >> 5, k = idx & 31;
            sX[m][k] = xbase[(size_t)m * NPIX + kk0 + k];
        }
        __syncthreads();
#pragma unroll 4
        for (int k = 0; k < 32; k++) {
            float a[8], xb[4];
#pragma unroll
            for (int i = 0; i < 8; i++) a[i] = sV[ty * 8 + i][k];
#pragma unroll
            for (int j = 0; j < 4; j++) xb[j] = sX[tx * 4 + j][k];
#pragma unroll
            for (int i = 0; i < 8; i++)
#pragma unroll
                for (int j = 0; j < 4; j++) acc[i][j] += a[i] * xb[j];
        }
        __syncthreads();
    }
    float* out = g_tpart + ((size_t)slice * BATCH + b) * CHN * 64;
#pragma unroll
    for (int i = 0; i < 8; i++)
#pragma unroll
        for (int j = 0; j < 4; j++)
            out[(ty * 8 + i) * 64 + tx * 4 + j] = acc[i][j];
}

// ---------------- solve: [G | t] -> G^{-1} t, in shared memory ---------------
// 768 threads = 4 row-groups x 192 columns. Augmented matrix 128 x 192 in smem.
__global__ __launch_bounds__(768) void solve_kernel()
{
    extern __shared__ float sA[];  // [128][192]
    __shared__ float fcol[128];
    __shared__ float prow[192];
    const int b = blockIdx.x, tid = threadIdx.x;

    for (int i = tid; i < 128 * 128; i += 768) {
        int r = i >> 7, c = i & 127;
        sA[r * 192 + c] = g_G[(size_t)b * CHN * CHN + i];
    }
    for (int e = tid; e < 128 * 64; e += 768) {
        int c = e >> 6, m = e & 63;
        float s = 0.f;
        for (int sl = 0; sl < NSLICE; sl++)
            s += g_tpart[((size_t)sl * BATCH + b) * CHN * 64 + e];
        sA[c * 192 + 128 + m] = s;
    }
    __syncthreads();

    const int j = tid % 192, g = tid / 192;
    for (int p = 0; p < 128; p++) {
        if (g == 0) {
            float piv = sA[p * 192 + p];
            prow[j] = sA[p * 192 + j] * (1.0f / piv);
        } else if (g == 1 && j < 128) {
            fcol[j] = (j == p) ? 0.f : sA[j * 192 + p];
        }
        __syncthreads();
        float pr = prow[j];
        const int i0 = g * 32;
#pragma unroll 4
        for (int i = i0; i < i0 + 32; i++) {
            float v = sA[i * 192 + j] - fcol[i] * pr;
            if (i == p) v = pr;
            sA[i * 192 + j] = v;
        }
        __syncthreads();
    }

    for (int e = tid; e < 128 * 64; e += 768)
        g_t2[(size_t)b * CHN * 64 + e] = sA[(e >> 6) * 192 + 128 + (e & 63)];
}

// ---------------- bridge[b][m][n] = sum_c V[c][n] * t2[c][m] -----------------
__global__ __launch_bounds__(256) void proj_kernel(float* __restrict__ out)
{
    __shared__ float st2[CHN * 64];
    __shared__ float sV[16][128];
    const int b = blockIdx.y;
    const int n0 = blockIdx.x * 128;
    const int tid = threadIdx.x, tx = tid & 31, ty = tid >> 5;
    for (int e = tid; e < CHN * 64; e += 256) st2[e] = g_t2[(size_t)b * CHN * 64 + e];

    float acc[8][4];
#pragma unroll
    for (int i = 0; i < 8; i++)
#pragma unroll
        for (int j = 0; j < 4; j++) acc[i][j] = 0.f;

    const float* Vb = g_feat + (size_t)b * CHN * NPIX;
    for (int cc = 0; cc < 8; cc++) {
        __syncthreads();
        for (int idx = tid; idx < 16 * 128; idx += 256) {
            int k = idx >> 7, px = idx & 127;
            sV[k][px] = Vb[(size_t)(cc * 16 + k) * NPIX + n0 + px];
        }
        __syncthreads();
#pragma unroll 4
        for (int k = 0; k < 16; k++) {
            int c = cc * 16 + k;
            float4 v4 = *(const float4*)&sV[k][tx * 4];
            float vv[4] = {v4.x, v4.y, v4.z, v4.w};
            float tm[8];
#pragma unroll
            for (int i = 0; i < 8; i++) tm[i] = st2[c * 64 + ty * 8 + i];
#pragma unroll
            for (int i = 0; i < 8; i++)
#pragma unroll
                for (int j = 0; j < 4; j++) acc[i][j] += tm[i] * vv[j];
        }
    }
#pragma unroll
    for (int i = 0; i < 8; i++) {
        int m = ty * 8 + i;
        float4 v;
        v.x = acc[i][0]; v.y = acc[i][1]; v.z = acc[i][2]; v.w = acc[i][3];
        *(float4*)&out[((size_t)b * 64 + m) * NPIX + n0 + tx * 4] = v;
    }
}

// ---------------- launch -----------------------------------------------------
extern "C" void kernel_launch(void* const* d_in, const int* in_sizes, int n_in,
                              void* d_out, int out_size)
{
    const float* x1 = (const float*)d_in[0];
    const float* x2 = (const float*)d_in[1];
    const float* w1 = (const float*)d_in[2];
    const float* b1 = (const float*)d_in[3];
    const float* w2 = (const float*)d_in[4];
    const float* b2 = (const float*)d_in[5];
    const float* wi = (const float*)d_in[6];
    const float* bi = (const float*)d_in[7];
    float* out = (float*)d_out;

    static bool attr_done = false;
    if (!attr_done) {
        cudaFuncSetAttribute(solve_kernel, cudaFuncAttributeMaxDynamicSharedMemorySize,
                             128 * 192 * sizeof(float));
        attr_done = true;
    }

    uint32_t* wr1;  cudaGetSymbolAddress((void**)&wr1, g_wr1);
    uint32_t* wr2;  cudaGetSymbolAddress((void**)&wr2, g_wr2);
    uint32_t* wir;  cudaGetSymbolAddress((void**)&wir, g_wir);

    repack_w3_kernel<<<144, 256>>>(w1, wr1);
    repack_w3_kernel<<<144, 256>>>(w2, wr2);
    repack_wi_kernel<<<16, 256>>>(wi, wir);

    dim3 cgrid(8, 16, 4);
    conv_mma_kernel<true><<<cgrid, 256>>>(x1, x2, b1, bi);
    conv_mma_kernel<false><<<cgrid, 256>>>(x1, x2, b2, nullptr);

    rowsum_scale_kernel<<<512, 256>>>();
    gemmG_kernel<<<dim3(NSLICE, BATCH), 256>>>();
    reduceG_kernel<<<256, 256>>>();
    gemmT_kernel<<<dim3(NSLICE, BATCH), 256>>>(x1);
    solve_kernel<<<BATCH, 768, 128 * 192 * sizeof(float)>>>();
    proj_kernel<<<dim3(128, BATCH), 256>>>(out);
}

// round 3
// speedup vs baseline: 3.6031x; 1.5259x over previous
#include <cuda_runtime.h>
#include <cstdint>
#include <cstddef>

#define NPIX 16384
#define CHN 128
#define BATCH 4
#define NSLICE 64

// ---------------- scratch (device globals; no allocation allowed) -------------
__device__ float g_cat[BATCH * CHN * NPIX];           // concat(x1,x2), tf32-rounded
__device__ float g_buf1[BATCH * CHN * NPIX];          // conv1 out (leaky, tf32-rounded)
__device__ float g_feat[BATCH * CHN * NPIX];          // 1x1 out, then feat, then V
__device__ float g_gpart[NSLICE * BATCH * CHN * CHN];
__device__ float g_G[BATCH * CHN * CHN];
__device__ float g_tpart[NSLICE * BATCH * CHN * 64];
__device__ float g_t2[BATCH * CHN * 64];
__device__ uint32_t g_wr1[16 * 9 * 8 * 32 * 4];       // repacked tf32 weight fragments
__device__ uint32_t g_wr2[16 * 9 * 8 * 32 * 4];
__device__ uint32_t g_wir[16 * 8 * 32 * 4];

__device__ __forceinline__ float leakyf(float v) { return v >= 0.f ? v : 0.2f * v; }

__device__ __forceinline__ uint32_t f2tf32(float f) {
    uint32_t o;
    asm("cvt.rna.tf32.f32 %0, %1;" : "=r"(o) : "f"(f));
    return o;
}
__device__ __forceinline__ float tf32r(float f) { return __uint_as_float(f2tf32(f)); }

__device__ __forceinline__ void mma_tf32(float* acc, const uint4& a, uint32_t b0, uint32_t b1) {
    asm volatile(
        "mma.sync.aligned.m16n8k8.row.col.f32.tf32.tf32.f32 "
        "{%0,%1,%2,%3}, {%4,%5,%6,%7}, {%8,%9}, {%0,%1,%2,%3};"
        : "+f"(acc[0]), "+f"(acc[1]), "+f"(acc[2]), "+f"(acc[3])
        : "r"(a.x), "r"(a.y), "r"(a.z), "r"(a.w), "r"(b0), "r"(b1));
}

__device__ __forceinline__ uint32_t smem_u32(const void* p) {
    return (uint32_t)__cvta_generic_to_shared(p);
}
__device__ __forceinline__ void cp16(uint32_t s, const void* g) {
    asm volatile("cp.async.cg.shared.global [%0], [%1], 16;" :: "r"(s), "l"(g));
}
__device__ __forceinline__ void cp4z(uint32_t s, const void* g, int valid) {
    asm volatile("cp.async.ca.shared.global [%0], [%1], 4, %2;" :: "r"(s), "l"(g), "r"(valid));
}
#define CP_COMMIT() asm volatile("cp.async.commit_group;")
#define CP_WAIT1() asm volatile("cp.async.wait_group 1;")
#define CP_WAIT0() asm volatile("cp.async.wait_group 0;")

// ---------------- prep: concat + tf32-round ----------------------------------
__global__ void prep_cat_kernel(const float* __restrict__ x1, const float* __restrict__ x2)
{
    int i4 = blockIdx.x * 256 + threadIdx.x;  // 2M float4
    if (i4 >= (BATCH * CHN * NPIX) / 4) return;
    size_t base = (size_t)i4 * 4;
    int b = (int)(base >> 21);
    int rem = (int)(base & ((1u << 21) - 1));
    int ic = rem >> 14;
    int n = rem & (NPIX - 1);
    const float* src = (ic < 64) ? x1 + ((size_t)(b * 64 + ic) << 14) + n
                                 : x2 + ((size_t)(b * 64 + ic - 64) << 14) + n;
    float4 v = *(const float4*)src;
    v.x = tf32r(v.x); v.y = tf32r(v.y); v.z = tf32r(v.z); v.w = tf32r(v.w);
    *(float4*)(g_cat + base) = v;
}

// ---------------- weight repack (fp32 -> tf32, fragment order) ---------------
__global__ void repack_w3_kernel(const float* __restrict__ w, uint32_t* __restrict__ out)
{
    int idx = blockIdx.x * 256 + threadIdx.x;
    if (idx >= 16 * 9 * 8 * 32) return;
    int lane = idx & 31;
    int t2 = idx >> 5;
    int ocg = t2 & 7;
    int t3 = t2 >> 3;
    int tap = t3 % 9;
    int chunk = t3 / 9;
    int oc = ocg * 16 + (lane >> 2);
    int ic = chunk * 8 + (lane & 3);
    uint32_t* o = out + (size_t)idx * 4;
    o[0] = f2tf32(w[((size_t)oc * CHN + ic) * 9 + tap]);
    o[1] = f2tf32(w[((size_t)(oc + 8) * CHN + ic) * 9 + tap]);
    o[2] = f2tf32(w[((size_t)oc * CHN + ic + 4) * 9 + tap]);
    o[3] = f2tf32(w[((size_t)(oc + 8) * CHN + ic + 4) * 9 + tap]);
}

__global__ void repack_wi_kernel(const float* __restrict__ wi, uint32_t* __restrict__ out)
{
    int idx = blockIdx.x * 256 + threadIdx.x;
    if (idx >= 16 * 8 * 32) return;
    int lane = idx & 31;
    int ocg = (idx >> 5) & 7;
    int chunk = idx >> 8;
    int oc = ocg * 16 + (lane >> 2);
    int ic = chunk * 8 + (lane & 3);
    uint32_t* o = out + (size_t)idx * 4;
    o[0] = f2tf32(wi[(size_t)oc * CHN + ic]);
    o[1] = f2tf32(wi[(size_t)(oc + 8) * CHN + ic]);
    o[2] = f2tf32(wi[(size_t)oc * CHN + ic + 4]);
    o[3] = f2tf32(wi[(size_t)(oc + 8) * CHN + ic + 4]);
}

// ---------------- conv 3x3 via tf32 mma, cp.async double-buffered ------------
// block 256 thr (8 warps): tile M=128 oc x N=128 px (8 rows x 16 cols)
// warpM = wid&3 (32 oc via 2 fragments), warpN = wid>>2 (4 rows x 16 px)
// smem: sW[2][9*8*32] uint4 (73728 B) + sIn[2][10*8*24] float (15360 B) = 89088 B
#define SW_CNT 2304
#define SIN_CNT 1920
#define CONV_SMEM 89088

template <bool FIRST>
__device__ __forceinline__ void conv_stage(int tid, int buf, int cc, int b, int r0, int c0,
                                           uint4* sW, float* sIn, const uint4* wsrc)
{
    const uint4* ws = wsrc + (size_t)cc * SW_CNT;
    uint4* wd = sW + buf * SW_CNT;
    for (int i = tid; i < SW_CNT; i += 256) cp16(smem_u32(wd + i), ws + i);

    const float* src = FIRST ? g_cat : g_buf1;
    const float* pb = src + ((size_t)b * CHN + cc * 8) * NPIX;
    float* ind = sIn + buf * SIN_CNT;
    for (int idx = tid; idx < 1440; idx += 256) {
        int r = idx / 144;
        int rem = idx - r * 144;
        int ic = rem / 18;
        int px = rem - ic * 18;
        int gr = r0 - 1 + r, gc = c0 - 1 + px;
        bool ok = ((unsigned)gr < 128u) && ((unsigned)gc < 128u);
        const float* g = pb + (size_t)ic * NPIX + (ok ? gr * 128 + gc : 0);
        cp4z(smem_u32(ind + (r * 8 + ic) * 24 + px), g, ok ? 4 : 0);
    }
}

template <bool FIRST>
__global__ __launch_bounds__(256, 2) void conv_mma_kernel(const float* __restrict__ bias)
{
    extern __shared__ char smem[];
    uint4* sW = (uint4*)smem;
    float* sIn = (float*)(smem + 73728);

    const int tid = threadIdx.x;
    const int lane = tid & 31;
    const int wid = tid >> 5;
    const int warpM = wid & 3;
    const int warpN = wid >> 2;
    const int lq = lane >> 2;
    const int lr = lane & 3;
    const int b = blockIdx.z;
    const int r0 = blockIdx.y * 8;
    const int c0 = blockIdx.x * 16;

    float acc[2][8][4];
#pragma unroll
    for (int m = 0; m < 2; m++)
#pragma unroll
        for (int j = 0; j < 8; j++)
#pragma unroll
            for (int e = 0; e < 4; e++) acc[m][j][e] = 0.f;

    const uint4* wsrc = (const uint4*)(FIRST ? g_wr1 : g_wr2);

    conv_stage<FIRST>(tid, 0, 0, b, r0, c0, sW, sIn, wsrc);
    CP_COMMIT();

    for (int cc = 0; cc < 16; cc++) {
        if (cc < 15) {
            conv_stage<FIRST>(tid, (cc + 1) & 1, cc + 1, b, r0, c0, sW, sIn, wsrc);
            CP_COMMIT();
            CP_WAIT1();
        } else {
            CP_WAIT0();
        }
        __syncthreads();

        const uint4* sWb = sW + (cc & 1) * SW_CNT;
        const float* sInb = sIn + (cc & 1) * SIN_CNT;
#pragma unroll
        for (int tap = 0; tap < 9; tap++) {
            const int dr = tap / 3, dc = tap % 3;
            uint4 af0 = sWb[(tap * 8 + warpM * 2 + 0) * 32 + lane];
            uint4 af1 = sWb[(tap * 8 + warpM * 2 + 1) * 32 + lane];
#pragma unroll
            for (int j = 0; j < 8; j++) {
                int row = warpN * 4 + (j >> 1) + dr;
                int pxb = (j & 1) * 8 + lq + dc;
                uint32_t b0 = __float_as_uint(sInb[(row * 8 + lr) * 24 + pxb]);
                uint32_t b1 = __float_as_uint(sInb[(row * 8 + lr + 4) * 24 + pxb]);
                mma_tf32(acc[0][j], af0, b0, b1);
                mma_tf32(acc[1][j], af1, b0, b1);
            }
        }
        __syncthreads();
    }

    // ---- epilogue ----
#pragma unroll
    for (int m = 0; m < 2; m++) {
        int oc = warpM * 32 + m * 16 + lq;
        float bv0 = bias[oc], bv1 = bias[oc + 8];
#pragma unroll
        for (int j = 0; j < 8; j++) {
            int irow = r0 + warpN * 4 + (j >> 1);
            int icol = c0 + (j & 1) * 8 + lr * 2;
            size_t base0 = ((size_t)(b * CHN + oc) * 128 + irow) * 128 + icol;
            size_t base1 = base0 + (size_t)8 * NPIX;
            if (FIRST) {
                float2 v0, v1;
                v0.x = tf32r(leakyf(acc[m][j][0] + bv0));
                v0.y = tf32r(leakyf(acc[m][j][1] + bv0));
                v1.x = tf32r(leakyf(acc[m][j][2] + bv1));
                v1.y = tf32r(leakyf(acc[m][j][3] + bv1));
                *(float2*)(g_buf1 + base0) = v0;
                *(float2*)(g_buf1 + base1) = v1;
            } else {
                float2 p0 = *(const float2*)(g_feat + base0);
                float2 p1 = *(const float2*)(g_feat + base1);
                p0.x += leakyf(acc[m][j][0] + bv0);
                p0.y += leakyf(acc[m][j][1] + bv0);
                p1.x += leakyf(acc[m][j][2] + bv1);
                p1.y += leakyf(acc[m][j][3] + bv1);
                *(float2*)(g_feat + base0) = p0;
                *(float2*)(g_feat + base1) = p1;
            }
        }
    }
}

// ---------------- 1x1 conv via tf32 mma: g_feat = wi @ cat + bi --------------
// block 256 thr (8 warps): tile 128 oc x 128 px; warp 32 oc x 64 px
__global__ __launch_bounds__(256) void gemm1x1_kernel(const float* __restrict__ bi)
{
    __shared__ float sB[2][8 * 136];

    const int tid = threadIdx.x;
    const int lane = tid & 31;
    const int wid = tid >> 5;
    const int warpM = wid & 3;
    const int warpN = wid >> 2;
    const int lq = lane >> 2;
    const int lr = lane & 3;
    const int b = blockIdx.y;
    const int px0 = blockIdx.x * 128;

    float acc[2][8][4];
#pragma unroll
    for (int m = 0; m < 2; m++)
#pragma unroll
        for (int j = 0; j < 8; j++)
#pragma unroll
            for (int e = 0; e < 4; e++) acc[m][j][e] = 0.f;

    const uint4* wsrc = (const uint4*)g_wir;

    // stage chunk 0
    {
        int ic = tid >> 5, q = tid & 31;
        cp16(smem_u32(&sB[0][ic * 136 + q * 4]),
             g_cat + ((size_t)(b * CHN + ic)) * NPIX + px0 + q * 4);
    }
    CP_COMMIT();

    for (int cc = 0; cc < 16; cc++) {
        if (cc < 15) {
            int ic = tid >> 5, q = tid & 31;
            cp16(smem_u32(&sB[(cc + 1) & 1][ic * 136 + q * 4]),
                 g_cat + ((size_t)(b * CHN + (cc + 1) * 8 + ic)) * NPIX + px0 + q * 4);
            CP_COMMIT();
            CP_WAIT1();
        } else {
            CP_WAIT0();
        }
        __syncthreads();

        const float* sBb = sB[cc & 1];
        uint4 wf0 = wsrc[(cc * 8 + warpM * 2 + 0) * 32 + lane];
        uint4 wf1 = wsrc[(cc * 8 + warpM * 2 + 1) * 32 + lane];
#pragma unroll
        for (int j = 0; j < 8; j++) {
            int pxb = warpN * 64 + j * 8 + lq;
            uint32_t b0 = __float_as_uint(sBb[lr * 136 + pxb]);
            uint32_t b1 = __float_as_uint(sBb[(lr + 4) * 136 + pxb]);
            mma_tf32(acc[0][j], wf0, b0, b1);
            mma_tf32(acc[1][j], wf1, b0, b1);
        }
        __syncthreads();
    }

#pragma unroll
    for (int m = 0; m < 2; m++) {
        int oc = warpM * 32 + m * 16 + lq;
        float b0 = bi[oc], b1 = bi[oc + 8];
#pragma unroll
        for (int j = 0; j < 8; j++) {
            int px = px0 + warpN * 64 + j * 8 + lr * 2;
            size_t base0 = ((size_t)(b * CHN + oc)) * NPIX + px;
            size_t base1 = base0 + (size_t)8 * NPIX;
            float2 v0, v1;
            v0.x = acc[m][j][0] + b0; v0.y = acc[m][j][1] + b0;
            v1.x = acc[m][j][2] + b1; v1.y = acc[m][j][3] + b1;
            *(float2*)(g_feat + base0) = v0;
            *(float2*)(g_feat + base1) = v1;
        }
    }
}

// ---------------- L1 row sums + in-place scale --------------------------------
__global__ void rowsum_scale_kernel()
{
    int bc = blockIdx.x;
    float* p = g_feat + (size_t)bc * NPIX;
    float s = 0.f;
    for (int i = threadIdx.x * 4; i < NPIX; i += 1024) {
        float4 v = *(const float4*)(p + i);
        s += fabsf(v.x) + fabsf(v.y) + fabsf(v.z) + fabsf(v.w);
    }
    __shared__ float red[256];
    red[threadIdx.x] = s;
    __syncthreads();
    for (int st = 128; st > 0; st >>= 1) {
        if (threadIdx.x < st) red[threadIdx.x] += red[threadIdx.x + st];
        __syncthreads();
    }
    float inv = 1.0f / (1e-6f + red[0]);
    for (int i = threadIdx.x * 4; i < NPIX; i += 1024) {
        float4 v = *(const float4*)(p + i);
        v.x *= inv; v.y *= inv; v.z *= inv; v.w *= inv;
        *(float4*)(p + i) = v;
    }
}

// ---------------- G = V V^T, split-K partials --------------------------------
__global__ __launch_bounds__(256) void gemmG_kernel()
{
    const int slice = blockIdx.x, b = blockIdx.y;
    const int k0 = slice * 256;
    __shared__ float sV[128][33];
    const int tid = threadIdx.x, tx = tid & 15, ty = tid >> 4;
    float acc[8][8];
#pragma unroll
    for (int i = 0; i < 8; i++)
#pragma unroll
        for (int j = 0; j < 8; j++) acc[i][j] = 0.f;

    const float* base = g_feat + (size_t)b * CHN * NPIX;
    for (int kt = 0; kt < 8; kt++) {
        int kk0 = k0 + kt * 32;
        for (int idx = tid; idx < 128 * 32; idx += 256) {
            int c = idx >> 5, k = idx & 31;
            sV[c][k] = base[(size_t)c * NPIX + kk0 + k];
        }
        __syncthreads();
#pragma unroll 4
        for (int k = 0; k < 32; k++) {
            float a[8], bb[8];
#pragma unroll
            for (int i = 0; i < 8; i++) a[i] = sV[ty * 8 + i][k];
#pragma unroll
            for (int j = 0; j < 8; j++) bb[j] = sV[tx * 8 + j][k];
#pragma unroll
            for (int i = 0; i < 8; i++)
#pragma unroll
                for (int j = 0; j < 8; j++) acc[i][j] += a[i] * bb[j];
        }
        __syncthreads();
    }
    float* out = g_gpart + ((size_t)slice * BATCH + b) * CHN * CHN;
#pragma unroll
    for (int i = 0; i < 8; i++)
#pragma unroll
        for (int j = 0; j < 8; j++)
            out[(ty * 8 + i) * 128 + tx * 8 + j] = acc[i][j];
}

__global__ void reduceG_kernel()
{
    int o = blockIdx.x * 256 + threadIdx.x;
    float s = 0.f;
    for (int sl = 0; sl < NSLICE; sl++)
        s += g_gpart[(size_t)sl * (BATCH * CHN * CHN) + o];
    g_G[o] = s;
}

// ---------------- t = V @ x1^T, split-K partials -----------------------------
__global__ __launch_bounds__(256) void gemmT_kernel(const float* __restrict__ x1)
{
    const int slice = blockIdx.x, b = blockIdx.y;
    const int k0 = slice * 256;
    __shared__ float sV[128][33];
    __shared__ float sX[64][33];
    const int tid = threadIdx.x, tx = tid & 15, ty = tid >> 4;
    float acc[8][4];
#pragma unroll
    for (int i = 0; i < 8; i++)
#pragma unroll
        for (int j = 0; j < 4; j++) acc[i][j] = 0.f;

    const float* vbase = g_feat + (size_t)b * CHN * NPIX;
    const float* xbase = x1 + (size_t)b * 64 * NPIX;
    for (int kt = 0; kt < 8; kt++) {
        int kk0 = k0 + kt * 32;
        for (int idx = tid; idx < 128 * 32; idx += 256) {
            int c = idx >> 5, k = idx & 31;
            sV[c][k] = vbase[(size_t)c * NPIX + kk0 + k];
        }
        for (int idx = tid; idx < 64 * 32; idx += 256) {
            int m = idx >> 5, k = idx & 31;
            sX[m][k] = xbase[(size_t)m * NPIX + kk0 + k];
        }
        __syncthreads();
#pragma unroll 4
        for (int k = 0; k < 32; k++) {
            float a[8], xb[4];
#pragma unroll
            for (int i = 0; i < 8; i++) a[i] = sV[ty * 8 + i][k];
#pragma unroll
            for (int j = 0; j < 4; j++) xb[j] = sX[tx * 4 + j][k];
#pragma unroll
            for (int i = 0; i < 8; i++)
#pragma unroll
                for (int j = 0; j < 4; j++) acc[i][j] += a[i] * xb[j];
        }
        __syncthreads();
    }
    float* out = g_tpart + ((size_t)slice * BATCH + b) * CHN * 64;
#pragma unroll
    for (int i = 0; i < 8; i++)
#pragma unroll
        for (int j = 0; j < 4; j++)
            out[(ty * 8 + i) * 64 + tx * 4 + j] = acc[i][j];
}

// ---------------- solve: [G | t] -> G^{-1} t, in shared memory ---------------
__global__ __launch_bounds__(768) void solve_kernel()
{
    extern __shared__ float sA[];  // [128][192]
    __shared__ float fcol[128];
    __shared__ float prow[192];
    const int b = blockIdx.x, tid = threadIdx.x;

    for (int i = tid; i < 128 * 128; i += 768) {
        int r = i >> 7, c = i & 127;
        sA[r * 192 + c] = g_G[(size_t)b * CHN * CHN + i];
    }
    for (int e = tid; e < 128 * 64; e += 768) {
        int c = e >> 6, m = e & 63;
        float s = 0.f;
        for (int sl = 0; sl < NSLICE; sl++)
            s += g_tpart[((size_t)sl * BATCH + b) * CHN * 64 + e];
        sA[c * 192 + 128 + m] = s;
    }
    __syncthreads();

    const int j = tid % 192, g = tid / 192;
    for (int p = 0; p < 128; p++) {
        if (g == 0) {
            float piv = sA[p * 192 + p];
            prow[j] = sA[p * 192 + j] * (1.0f / piv);
        } else if (g == 1 && j < 128) {
            fcol[j] = (j == p) ? 0.f : sA[j * 192 + p];
        }
        __syncthreads();
        float pr = prow[j];
        const int i0 = g * 32;
#pragma unroll 4
        for (int i = i0; i < i0 + 32; i++) {
            float v = sA[i * 192 + j] - fcol[i] * pr;
            if (i == p) v = pr;
            sA[i * 192 + j] = v;
        }
        __syncthreads();
    }

    for (int e = tid; e < 128 * 64; e += 768)
        g_t2[(size_t)b * CHN * 64 + e] = sA[(e >> 6) * 192 + 128 + (e & 63)];
}

// ---------------- bridge[b][m][n] = sum_c V[c][n] * t2[c][m] -----------------
__global__ __launch_bounds__(256) void proj_kernel(float* __restrict__ out)
{
    __shared__ float st2[CHN * 64];
    __shared__ float sV[16][128];
    const int b = blockIdx.y;
    const int n0 = blockIdx.x * 128;
    const int tid = threadIdx.x, tx = tid & 31, ty = tid >> 5;
    for (int e = tid; e < CHN * 64; e += 256) st2[e] = g_t2[(size_t)b * CHN * 64 + e];

    float acc[8][4];
#pragma unroll
    for (int i = 0; i < 8; i++)
#pragma unroll
        for (int j = 0; j < 4; j++) acc[i][j] = 0.f;

    const float* Vb = g_feat + (size_t)b * CHN * NPIX;
    for (int cc = 0; cc < 8; cc++) {
        __syncthreads();
        for (int idx = tid; idx < 16 * 128; idx += 256) {
            int k = idx >> 7, px = idx & 127;
            sV[k][px] = Vb[(size_t)(cc * 16 + k) * NPIX + n0 + px];
        }
        __syncthreads();
#pragma unroll 4
        for (int k = 0; k < 16; k++) {
            int c = cc * 16 + k;
            float4 v4 = *(const float4*)&sV[k][tx * 4];
            float vv[4] = {v4.x, v4.y, v4.z, v4.w};
            float tm[8];
#pragma unroll
            for (int i = 0; i < 8; i++) tm[i] = st2[c * 64 + ty * 8 + i];
#pragma unroll
            for (int i = 0; i < 8; i++)
#pragma unroll
                for (int j = 0; j < 4; j++) acc[i][j] += tm[i] * vv[j];
        }
    }
#pragma unroll
    for (int i = 0; i < 8; i++) {
        int m = ty * 8 + i;
        float4 v;
        v.x = acc[i][0]; v.y = acc[i][1]; v.z = acc[i][2]; v.w = acc[i][3];
        *(float4*)&out[((size_t)b * 64 + m) * NPIX + n0 + tx * 4] = v;
    }
}

// ---------------- launch -----------------------------------------------------
extern "C" void kernel_launch(void* const* d_in, const int* in_sizes, int n_in,
                              void* d_out, int out_size)
{
    const float* x1 = (const float*)d_in[0];
    const float* x2 = (const float*)d_in[1];
    const float* w1 = (const float*)d_in[2];
    const float* b1 = (const float*)d_in[3];
    const float* w2 = (const float*)d_in[4];
    const float* b2 = (const float*)d_in[5];
    const float* wi = (const float*)d_in[6];
    const float* bi = (const float*)d_in[7];
    float* out = (float*)d_out;

    static bool attr_done = false;
    if (!attr_done) {
        cudaFuncSetAttribute(solve_kernel, cudaFuncAttributeMaxDynamicSharedMemorySize,
                             128 * 192 * sizeof(float));
        cudaFuncSetAttribute(conv_mma_kernel<true>,
                             cudaFuncAttributeMaxDynamicSharedMemorySize, CONV_SMEM);
        cudaFuncSetAttribute(conv_mma_kernel<false>,
                             cudaFuncAttributeMaxDynamicSharedMemorySize, CONV_SMEM);
        attr_done = true;
    }

    uint32_t* wr1;  cudaGetSymbolAddress((void**)&wr1, g_wr1);
    uint32_t* wr2;  cudaGetSymbolAddress((void**)&wr2, g_wr2);
    uint32_t* wir;  cudaGetSymbolAddress((void**)&wir, g_wir);

    prep_cat_kernel<<<8192, 256>>>(x1, x2);
    repack_w3_kernel<<<144, 256>>>(w1, wr1);
    repack_w3_kernel<<<144, 256>>>(w2, wr2);
    repack_wi_kernel<<<16, 256>>>(wi, wir);

    dim3 cgrid(8, 16, 4);
    conv_mma_kernel<true><<<cgrid, 256, CONV_SMEM>>>(b1);
    gemm1x1_kernel<<<dim3(128, 4), 256>>>(bi);
    conv_mma_kernel<false><<<cgrid, 256, CONV_SMEM>>>(b2);

    rowsum_scale_kernel<<<512, 256>>>();
    gemmG_kernel<<<dim3(NSLICE, BATCH), 256>>>();
    reduceG_kernel<<<256, 256>>>();
    gemmT_kernel<<<dim3(NSLICE, BATCH), 256>>>(x1);
    solve_kernel<<<BATCH, 768, 128 * 192 * sizeof(float)>>>();
    proj_kernel<<<dim3(128, BATCH), 256>>>(out);
}

// round 4
// speedup vs baseline: 4.5511x; 1.2631x over previous
#include <cuda_runtime.h>
#include <cstdint>
#include <cstddef>

#define NPIX 16384
#define CHN 128
#define BATCH 4
#define NSLICE 64

// ---------------- scratch (device globals; no allocation allowed) -------------
__device__ float g_cat[BATCH * CHN * NPIX];           // concat(x1,x2), tf32-rounded
__device__ float g_buf1[BATCH * CHN * NPIX];          // conv1 out (leaky, tf32-rounded)
__device__ float g_feat[BATCH * CHN * NPIX];          // 1x1 out, then feat, then V
__device__ float g_gpart[NSLICE * BATCH * CHN * CHN];
__device__ float g_G[BATCH * CHN * CHN];
__device__ float g_tpart[NSLICE * BATCH * CHN * 64];
__device__ float g_t2[BATCH * CHN * 64];
__device__ uint32_t g_wr1[16 * 9 * 8 * 32 * 4];       // repacked tf32 weight fragments
__device__ uint32_t g_wr2[16 * 9 * 8 * 32 * 4];
__device__ uint32_t g_wir[16 * 8 * 32 * 4];

__device__ __forceinline__ float leakyf(float v) { return v >= 0.f ? v : 0.2f * v; }

__device__ __forceinline__ uint32_t f2tf32(float f) {
    uint32_t o;
    asm("cvt.rna.tf32.f32 %0, %1;" : "=r"(o) : "f"(f));
    return o;
}
__device__ __forceinline__ float tf32r(float f) { return __uint_as_float(f2tf32(f)); }

__device__ __forceinline__ void mma_tf32(float* acc, const uint4& a, uint32_t b0, uint32_t b1) {
    asm volatile(
        "mma.sync.aligned.m16n8k8.row.col.f32.tf32.tf32.f32 "
        "{%0,%1,%2,%3}, {%4,%5,%6,%7}, {%8,%9}, {%0,%1,%2,%3};"
        : "+f"(acc[0]), "+f"(acc[1]), "+f"(acc[2]), "+f"(acc[3])
        : "r"(a.x), "r"(a.y), "r"(a.z), "r"(a.w), "r"(b0), "r"(b1));
}

__device__ __forceinline__ uint32_t smem_u32(const void* p) {
    return (uint32_t)__cvta_generic_to_shared(p);
}
__device__ __forceinline__ void cp16(uint32_t s, const void* g) {
    asm volatile("cp.async.cg.shared.global [%0], [%1], 16;" :: "r"(s), "l"(g));
}
__device__ __forceinline__ void cp4z(uint32_t s, const void* g, int valid) {
    asm volatile("cp.async.ca.shared.global [%0], [%1], 4, %2;" :: "r"(s), "l"(g), "r"(valid));
}
#define CP_COMMIT() asm volatile("cp.async.commit_group;")
#define CP_WAIT1() asm volatile("cp.async.wait_group 1;")
#define CP_WAIT0() asm volatile("cp.async.wait_group 0;")

// ---------------- prep: concat + tf32-round ----------------------------------
__global__ void prep_cat_kernel(const float* __restrict__ x1, const float* __restrict__ x2)
{
    int i4 = blockIdx.x * 256 + threadIdx.x;
    if (i4 >= (BATCH * CHN * NPIX) / 4) return;
    size_t base = (size_t)i4 * 4;
    int b = (int)(base >> 21);
    int rem = (int)(base & ((1u << 21) - 1));
    int ic = rem >> 14;
    int n = rem & (NPIX - 1);
    const float* src = (ic < 64) ? x1 + ((size_t)(b * 64 + ic) << 14) + n
                                 : x2 + ((size_t)(b * 64 + ic - 64) << 14) + n;
    float4 v = *(const float4*)src;
    v.x = tf32r(v.x); v.y = tf32r(v.y); v.z = tf32r(v.z); v.w = tf32r(v.w);
    *(float4*)(g_cat + base) = v;
}

// ---------------- weight repack (all 3 in one launch) -------------------------
__device__ __forceinline__ void repack_w3(const float* __restrict__ w, uint32_t* __restrict__ out,
                                          int idx)
{
    int lane = idx & 31;
    int t2 = idx >> 5;
    int ocg = t2 & 7;
    int t3 = t2 >> 3;
    int tap = t3 % 9;
    int chunk = t3 / 9;
    int oc = ocg * 16 + (lane >> 2);
    int ic = chunk * 8 + (lane & 3);
    uint32_t* o = out + (size_t)idx * 4;
    o[0] = f2tf32(w[((size_t)oc * CHN + ic) * 9 + tap]);
    o[1] = f2tf32(w[((size_t)(oc + 8) * CHN + ic) * 9 + tap]);
    o[2] = f2tf32(w[((size_t)oc * CHN + ic + 4) * 9 + tap]);
    o[3] = f2tf32(w[((size_t)(oc + 8) * CHN + ic + 4) * 9 + tap]);
}

__global__ void repack_all_kernel(const float* __restrict__ w1, const float* __restrict__ w2,
                                  const float* __restrict__ wi,
                                  uint32_t* __restrict__ wr1, uint32_t* __restrict__ wr2,
                                  uint32_t* __restrict__ wir)
{
    int bx = blockIdx.x;
    if (bx < 144) {
        int idx = bx * 256 + threadIdx.x;
        if (idx < 16 * 9 * 8 * 32) repack_w3(w1, wr1, idx);
    } else if (bx < 288) {
        int idx = (bx - 144) * 256 + threadIdx.x;
        if (idx < 16 * 9 * 8 * 32) repack_w3(w2, wr2, idx);
    } else {
        int idx = (bx - 288) * 256 + threadIdx.x;
        if (idx >= 16 * 8 * 32) return;
        int lane = idx & 31;
        int ocg = (idx >> 5) & 7;
        int chunk = idx >> 8;
        int oc = ocg * 16 + (lane >> 2);
        int ic = chunk * 8 + (lane & 3);
        uint32_t* o = wir + (size_t)idx * 4;
        o[0] = f2tf32(wi[(size_t)oc * CHN + ic]);
        o[1] = f2tf32(wi[(size_t)(oc + 8) * CHN + ic]);
        o[2] = f2tf32(wi[(size_t)oc * CHN + ic + 4]);
        o[3] = f2tf32(wi[(size_t)(oc + 8) * CHN + ic + 4]);
    }
}

// ---------------- conv 3x3 via tf32 mma, cp.async double-buffered ------------
#define SW_CNT 2304
#define SIN_CNT 1920
#define CONV_SMEM 89088

template <bool FIRST>
__device__ __forceinline__ void conv_stage(int tid, int buf, int cc, int b, int r0, int c0,
                                           uint4* sW, float* sIn, const uint4* wsrc)
{
    const uint4* ws = wsrc + (size_t)cc * SW_CNT;
    uint4* wd = sW + buf * SW_CNT;
    for (int i = tid; i < SW_CNT; i += 256) cp16(smem_u32(wd + i), ws + i);

    const float* src = FIRST ? g_cat : g_buf1;
    const float* pb = src + ((size_t)b * CHN + cc * 8) * NPIX;
    float* ind = sIn + buf * SIN_CNT;
    for (int idx = tid; idx < 1440; idx += 256) {
        int r = idx / 144;
        int rem = idx - r * 144;
        int ic = rem / 18;
        int px = rem - ic * 18;
        int gr = r0 - 1 + r, gc = c0 - 1 + px;
        bool ok = ((unsigned)gr < 128u) && ((unsigned)gc < 128u);
        const float* g = pb + (size_t)ic * NPIX + (ok ? gr * 128 + gc : 0);
        cp4z(smem_u32(ind + (r * 8 + ic) * 24 + px), g, ok ? 4 : 0);
    }
}

template <bool FIRST>
__global__ __launch_bounds__(256, 2) void conv_mma_kernel(const float* __restrict__ bias)
{
    extern __shared__ char smem[];
    uint4* sW = (uint4*)smem;
    float* sIn = (float*)(smem + 73728);

    const int tid = threadIdx.x;
    const int lane = tid & 31;
    const int wid = tid >> 5;
    const int warpM = wid & 3;
    const int warpN = wid >> 2;
    const int lq = lane >> 2;
    const int lr = lane & 3;
    const int b = blockIdx.z;
    const int r0 = blockIdx.y * 8;
    const int c0 = blockIdx.x * 16;

    float acc[2][8][4];
#pragma unroll
    for (int m = 0; m < 2; m++)
#pragma unroll
        for (int j = 0; j < 8; j++)
#pragma unroll
            for (int e = 0; e < 4; e++) acc[m][j][e] = 0.f;

    const uint4* wsrc = (const uint4*)(FIRST ? g_wr1 : g_wr2);

    conv_stage<FIRST>(tid, 0, 0, b, r0, c0, sW, sIn, wsrc);
    CP_COMMIT();

    for (int cc = 0; cc < 16; cc++) {
        if (cc < 15) {
            conv_stage<FIRST>(tid, (cc + 1) & 1, cc + 1, b, r0, c0, sW, sIn, wsrc);
            CP_COMMIT();
            CP_WAIT1();
        } else {
            CP_WAIT0();
        }
        __syncthreads();

        const uint4* sWb = sW + (cc & 1) * SW_CNT;
        const float* sInb = sIn + (cc & 1) * SIN_CNT;
#pragma unroll
        for (int tap = 0; tap < 9; tap++) {
            const int dr = tap / 3, dc = tap % 3;
            uint4 af0 = sWb[(tap * 8 + warpM * 2 + 0) * 32 + lane];
            uint4 af1 = sWb[(tap * 8 + warpM * 2 + 1) * 32 + lane];
#pragma unroll
            for (int j = 0; j < 8; j++) {
                int row = warpN * 4 + (j >> 1) + dr;
                int pxb = (j & 1) * 8 + lq + dc;
                uint32_t b0 = __float_as_uint(sInb[(row * 8 + lr) * 24 + pxb]);
                uint32_t b1 = __float_as_uint(sInb[(row * 8 + lr + 4) * 24 + pxb]);
                mma_tf32(acc[0][j], af0, b0, b1);
                mma_tf32(acc[1][j], af1, b0, b1);
            }
        }
        __syncthreads();
    }

#pragma unroll
    for (int m = 0; m < 2; m++) {
        int oc = warpM * 32 + m * 16 + lq;
        float bv0 = bias[oc], bv1 = bias[oc + 8];
#pragma unroll
        for (int j = 0; j < 8; j++) {
            int irow = r0 + warpN * 4 + (j >> 1);
            int icol = c0 + (j & 1) * 8 + lr * 2;
            size_t base0 = ((size_t)(b * CHN + oc) * 128 + irow) * 128 + icol;
            size_t base1 = base0 + (size_t)8 * NPIX;
            if (FIRST) {
                float2 v0, v1;
                v0.x = tf32r(leakyf(acc[m][j][0] + bv0));
                v0.y = tf32r(leakyf(acc[m][j][1] + bv0));
                v1.x = tf32r(leakyf(acc[m][j][2] + bv1));
                v1.y = tf32r(leakyf(acc[m][j][3] + bv1));
                *(float2*)(g_buf1 + base0) = v0;
                *(float2*)(g_buf1 + base1) = v1;
            } else {
                float2 p0 = *(const float2*)(g_feat + base0);
                float2 p1 = *(const float2*)(g_feat + base1);
                p0.x += leakyf(acc[m][j][0] + bv0);
                p0.y += leakyf(acc[m][j][1] + bv0);
                p1.x += leakyf(acc[m][j][2] + bv1);
                p1.y += leakyf(acc[m][j][3] + bv1);
                *(float2*)(g_feat + base0) = p0;
                *(float2*)(g_feat + base1) = p1;
            }
        }
    }
}

// ---------------- 1x1 conv via tf32 mma: g_feat = wi @ cat + bi --------------
__global__ __launch_bounds__(256) void gemm1x1_kernel(const float* __restrict__ bi)
{
    __shared__ float sB[2][8 * 136];

    const int tid = threadIdx.x;
    const int lane = tid & 31;
    const int wid = tid >> 5;
    const int warpM = wid & 3;
    const int warpN = wid >> 2;
    const int lq = lane >> 2;
    const int lr = lane & 3;
    const int b = blockIdx.y;
    const int px0 = blockIdx.x * 128;

    float acc[2][8][4];
#pragma unroll
    for (int m = 0; m < 2; m++)
#pragma unroll
        for (int j = 0; j < 8; j++)
#pragma unroll
            for (int e = 0; e < 4; e++) acc[m][j][e] = 0.f;

    const uint4* wsrc = (const uint4*)g_wir;

    {
        int ic = tid >> 5, q = tid & 31;
        cp16(smem_u32(&sB[0][ic * 136 + q * 4]),
             g_cat + ((size_t)(b * CHN + ic)) * NPIX + px0 + q * 4);
    }
    CP_COMMIT();

    for (int cc = 0; cc < 16; cc++) {
        if (cc < 15) {
            int ic = tid >> 5, q = tid & 31;
            cp16(smem_u32(&sB[(cc + 1) & 1][ic * 136 + q * 4]),
                 g_cat + ((size_t)(b * CHN + (cc + 1) * 8 + ic)) * NPIX + px0 + q * 4);
            CP_COMMIT();
            CP_WAIT1();
        } else {
            CP_WAIT0();
        }
        __syncthreads();

        const float* sBb = sB[cc & 1];
        uint4 wf0 = wsrc[(cc * 8 + warpM * 2 + 0) * 32 + lane];
        uint4 wf1 = wsrc[(cc * 8 + warpM * 2 + 1) * 32 + lane];
#pragma unroll
        for (int j = 0; j < 8; j++) {
            int pxb = warpN * 64 + j * 8 + lq;
            uint32_t b0 = __float_as_uint(sBb[lr * 136 + pxb]);
            uint32_t b1 = __float_as_uint(sBb[(lr + 4) * 136 + pxb]);
            mma_tf32(acc[0][j], wf0, b0, b1);
            mma_tf32(acc[1][j], wf1, b0, b1);
        }
        __syncthreads();
    }

#pragma unroll
    for (int m = 0; m < 2; m++) {
        int oc = warpM * 32 + m * 16 + lq;
        float b0 = bi[oc], b1 = bi[oc + 8];
#pragma unroll
        for (int j = 0; j < 8; j++) {
            int px = px0 + warpN * 64 + j * 8 + lr * 2;
            size_t base0 = ((size_t)(b * CHN + oc)) * NPIX + px;
            size_t base1 = base0 + (size_t)8 * NPIX;
            float2 v0, v1;
            v0.x = acc[m][j][0] + b0; v0.y = acc[m][j][1] + b0;
            v1.x = acc[m][j][2] + b1; v1.y = acc[m][j][3] + b1;
            *(float2*)(g_feat + base0) = v0;
            *(float2*)(g_feat + base1) = v1;
        }
    }
}

// ---------------- L1 row sums + in-place scale --------------------------------
__global__ void rowsum_scale_kernel()
{
    int bc = blockIdx.x;
    float* p = g_feat + (size_t)bc * NPIX;
    float s = 0.f;
    for (int i = threadIdx.x * 4; i < NPIX; i += 1024) {
        float4 v = *(const float4*)(p + i);
        s += fabsf(v.x) + fabsf(v.y) + fabsf(v.z) + fabsf(v.w);
    }
    __shared__ float red[256];
    red[threadIdx.x] = s;
    __syncthreads();
    for (int st = 128; st > 0; st >>= 1) {
        if (threadIdx.x < st) red[threadIdx.x] += red[threadIdx.x + st];
        __syncthreads();
    }
    float inv = 1.0f / (1e-6f + red[0]);
    for (int i = threadIdx.x * 4; i < NPIX; i += 1024) {
        float4 v = *(const float4*)(p + i);
        v.x *= inv; v.y *= inv; v.z *= inv; v.w *= inv;
        *(float4*)(p + i) = v;
    }
}

// ---------------- G = V V^T via tf32 mma, split-K -----------------------------
// CTA: 128x128 output, K-slice 256 (16 chunks of 16). sV[c][k] stride 20.
// Warp tile 32(m) x 64(n): mfrag 2, nfrag 8.
__global__ __launch_bounds__(256, 2) void gemmG_mma_kernel()
{
    __shared__ float sV[2][128 * 20];
    const int tid = threadIdx.x;
    const int lane = tid & 31;
    const int wid = tid >> 5;
    const int warpM = wid & 3;
    const int warpN = wid >> 2;
    const int lq = lane >> 2;
    const int lr = lane & 3;
    const int slice = blockIdx.x, b = blockIdx.y;
    const float* base = g_feat + (size_t)b * CHN * NPIX;
    const int k0g = slice * 256;

    float acc[2][8][4];
#pragma unroll
    for (int mi = 0; mi < 2; mi++)
#pragma unroll
        for (int nj = 0; nj < 8; nj++)
#pragma unroll
            for (int e = 0; e < 4; e++) acc[mi][nj][e] = 0.f;

    // stage chunk 0: 128 c x 16 k = 512 float4
    {
        int c = tid >> 1, q = tid & 1;
        cp16(smem_u32(&sV[0][c * 20 + q * 8]), base + (size_t)c * NPIX + k0g + q * 8);
        cp16(smem_u32(&sV[0][c * 20 + q * 8 + 4]), base + (size_t)c * NPIX + k0g + q * 8 + 4);
    }
    CP_COMMIT();

    for (int kc = 0; kc < 16; kc++) {
        if (kc < 15) {
            int c = tid >> 1, q = tid & 1;
            int kk = k0g + (kc + 1) * 16;
            cp16(smem_u32(&sV[(kc + 1) & 1][c * 20 + q * 8]), base + (size_t)c * NPIX + kk + q * 8);
            cp16(smem_u32(&sV[(kc + 1) & 1][c * 20 + q * 8 + 4]),
                 base + (size_t)c * NPIX + kk + q * 8 + 4);
            CP_COMMIT();
            CP_WAIT1();
        } else {
            CP_WAIT0();
        }
        __syncthreads();
        const float* sv = sV[kc & 1];
#pragma unroll
        for (int ks = 0; ks < 2; ks++) {
            int k = ks * 8;
            uint4 af[2];
#pragma unroll
            for (int mi = 0; mi < 2; mi++) {
                int m0 = warpM * 32 + mi * 16;
                af[mi].x = __float_as_uint(sv[(m0 + lq) * 20 + k + lr]);
                af[mi].y = __float_as_uint(sv[(m0 + lq + 8) * 20 + k + lr]);
                af[mi].z = __float_as_uint(sv[(m0 + lq) * 20 + k + lr + 4]);
                af[mi].w = __float_as_uint(sv[(m0 + lq + 8) * 20 + k + lr + 4]);
            }
#pragma unroll
            for (int nj = 0; nj < 8; nj++) {
                int n0 = warpN * 64 + nj * 8;
                uint32_t b0 = __float_as_uint(sv[(n0 + lq) * 20 + k + lr]);
                uint32_t b1 = __float_as_uint(sv[(n0 + lq) * 20 + k + lr + 4]);
                mma_tf32(acc[0][nj], af[0], b0, b1);
                mma_tf32(acc[1][nj], af[1], b0, b1);
            }
        }
        __syncthreads();
    }

    float* outp = g_gpart + ((size_t)slice * BATCH + b) * CHN * CHN;
#pragma unroll
    for (int mi = 0; mi < 2; mi++) {
        int m0 = warpM * 32 + mi * 16 + lq;
#pragma unroll
        for (int nj = 0; nj < 8; nj++) {
            int n = warpN * 64 + nj * 8 + lr * 2;
            *(float2*)(outp + m0 * 128 + n) = make_float2(acc[mi][nj][0], acc[mi][nj][1]);
            *(float2*)(outp + (m0 + 8) * 128 + n) = make_float2(acc[mi][nj][2], acc[mi][nj][3]);
        }
    }
}

__global__ void reduceG_kernel()
{
    int o = blockIdx.x * 256 + threadIdx.x;
    float s = 0.f;
    for (int sl = 0; sl < NSLICE; sl++)
        s += g_gpart[(size_t)sl * (BATCH * CHN * CHN) + o];
    g_G[o] = s;
}

// ---------------- t = V @ x1^T via tf32 mma, split-K --------------------------
// CTA: 128(c) x 64(m) output, K-slice 256. Warp tile 32x32: mfrag 2, nfrag 4.
__global__ __launch_bounds__(256, 2) void gemmT_mma_kernel()
{
    __shared__ float sV[2][128 * 20];
    __shared__ float sX[2][64 * 20];
    const int tid = threadIdx.x;
    const int lane = tid & 31;
    const int wid = tid >> 5;
    const int warpM = wid & 3;
    const int warpN = wid >> 2;
    const int lq = lane >> 2;
    const int lr = lane & 3;
    const int slice = blockIdx.x, b = blockIdx.y;
    const float* vbase = g_feat + (size_t)b * CHN * NPIX;
    const float* xbase = g_cat + (size_t)b * CHN * NPIX;  // channels 0..63 = tf32(x1)
    const int k0g = slice * 256;

    float acc[2][4][4];
#pragma unroll
    for (int mi = 0; mi < 2; mi++)
#pragma unroll
        for (int nj = 0; nj < 4; nj++)
#pragma unroll
            for (int e = 0; e < 4; e++) acc[mi][nj][e] = 0.f;

    auto stage = [&](int buf, int kc) {
        int kk = k0g + kc * 16;
        int c = tid >> 1, q = tid & 1;
        cp16(smem_u32(&sV[buf][c * 20 + q * 8]), vbase + (size_t)c * NPIX + kk + q * 8);
        cp16(smem_u32(&sV[buf][c * 20 + q * 8 + 4]), vbase + (size_t)c * NPIX + kk + q * 8 + 4);
        int m = tid >> 2, q2 = tid & 3;
        cp16(smem_u32(&sX[buf][m * 20 + q2 * 4]), xbase + (size_t)m * NPIX + kk + q2 * 4);
    };

    stage(0, 0);
    CP_COMMIT();

    for (int kc = 0; kc < 16; kc++) {
        if (kc < 15) {
            stage((kc + 1) & 1, kc + 1);
            CP_COMMIT();
            CP_WAIT1();
        } else {
            CP_WAIT0();
        }
        __syncthreads();
        const float* sv = sV[kc & 1];
        const float* sx = sX[kc & 1];
#pragma unroll
        for (int ks = 0; ks < 2; ks++) {
            int k = ks * 8;
            uint4 af[2];
#pragma unroll
            for (int mi = 0; mi < 2; mi++) {
                int m0 = warpM * 32 + mi * 16;
                af[mi].x = __float_as_uint(sv[(m0 + lq) * 20 + k + lr]);
                af[mi].y = __float_as_uint(sv[(m0 + lq + 8) * 20 + k + lr]);
                af[mi].z = __float_as_uint(sv[(m0 + lq) * 20 + k + lr + 4]);
                af[mi].w = __float_as_uint(sv[(m0 + lq + 8) * 20 + k + lr + 4]);
            }
#pragma unroll
            for (int nj = 0; nj < 4; nj++) {
                int n0 = warpN * 32 + nj * 8;
                uint32_t b0 = __float_as_uint(sx[(n0 + lq) * 20 + k + lr]);
                uint32_t b1 = __float_as_uint(sx[(n0 + lq) * 20 + k + lr + 4]);
                mma_tf32(acc[0][nj], af[0], b0, b1);
                mma_tf32(acc[1][nj], af[1], b0, b1);
            }
        }
        __syncthreads();
    }

    float* outp = g_tpart + ((size_t)slice * BATCH + b) * CHN * 64;
#pragma unroll
    for (int mi = 0; mi < 2; mi++) {
        int m0 = warpM * 32 + mi * 16 + lq;
#pragma unroll
        for (int nj = 0; nj < 4; nj++) {
            int n = warpN * 32 + nj * 8 + lr * 2;
            *(float2*)(outp + m0 * 64 + n) = make_float2(acc[mi][nj][0], acc[mi][nj][1]);
            *(float2*)(outp + (m0 + 8) * 64 + n) = make_float2(acc[mi][nj][2], acc[mi][nj][3]);
        }
    }
}

// ---------------- solve: [G | t] -> G^{-1} t, in shared memory ---------------
__global__ __launch_bounds__(768) void solve_kernel()
{
    extern __shared__ float sA[];  // [128][192]
    __shared__ float fcol[128];
    __shared__ float prow[192];
    const int b = blockIdx.x, tid = threadIdx.x;

    for (int i = tid; i < 128 * 128; i += 768) {
        int r = i >> 7, c = i & 127;
        sA[r * 192 + c] = g_G[(size_t)b * CHN * CHN + i];
    }
    for (int e = tid; e < 128 * 64; e += 768) {
        float s = 0.f;
        for (int sl = 0; sl < NSLICE; sl++)
            s += g_tpart[((size_t)sl * BATCH + b) * CHN * 64 + e];
        sA[(e >> 6) * 192 + 128 + (e & 63)] = s;
    }
    __syncthreads();

    const int j = tid % 192, g = tid / 192;
    for (int p = 0; p < 128; p++) {
        if (g == 0) {
            float piv = sA[p * 192 + p];
            prow[j] = sA[p * 192 + j] * (1.0f / piv);
        } else if (g == 1 && j < 128) {
            fcol[j] = (j == p) ? 0.f : sA[j * 192 + p];
        }
        __syncthreads();
        float pr = prow[j];
        const int i0 = g * 32;
#pragma unroll 4
        for (int i = i0; i < i0 + 32; i++) {
            float v = sA[i * 192 + j] - fcol[i] * pr;
            if (i == p) v = pr;
            sA[i * 192 + j] = v;
        }
        __syncthreads();
    }

    for (int e = tid; e < 128 * 64; e += 768)
        g_t2[(size_t)b * CHN * 64 + e] = sA[(e >> 6) * 192 + 128 + (e & 63)];
}

// ---------------- proj via tf32 mma: out[m][n] = sum_c t2[c][m] V[c][n] ------
// CTA: 64(m) x 256(n), K=128 (16 chunks of 8 c). 8 warps = 8 n-slices of 32.
// smem: st2[128][72] + sVc[2][8][264] (dynamic, 53760 B)
#define PROJ_SMEM (128 * 72 * 4 + 2 * 8 * 264 * 4)
__global__ __launch_bounds__(256, 2) void proj_mma_kernel(float* __restrict__ out)
{
    extern __shared__ float psm[];
    float* st2 = psm;                 // [128][72]
    float* sVc = psm + 128 * 72;      // [2][8][264]

    const int tid = threadIdx.x;
    const int lane = tid & 31;
    const int wid = tid >> 5;
    const int lq = lane >> 2;
    const int lr = lane & 3;
    const int b = blockIdx.y;
    const int n0cta = blockIdx.x * 256;
    const float* Vb = g_feat + (size_t)b * CHN * NPIX;

    // stage t2 (cp.async group 0 stays pending alongside chunk groups; waited via WAIT)
    {
        int e4 = tid;  // 128*64/4 = 2048 float4 -> 8 per thread
        for (int i = 0; i < 8; i++, e4 += 256) {
            int c = e4 >> 4, mq = e4 & 15;
            cp16(smem_u32(st2 + c * 72 + mq * 4), g_t2 + (size_t)b * CHN * 64 + c * 64 + mq * 4);
        }
    }
    auto stageV = [&](int buf, int cc) {
        int r = tid >> 6, q = tid & 63;  // 2 rows per pass
        cp16(smem_u32(sVc + buf * 8 * 264 + r * 264 + q * 4),
             Vb + (size_t)(cc * 8 + r) * NPIX + n0cta + q * 4);
        cp16(smem_u32(sVc + buf * 8 * 264 + (r + 4) * 264 + q * 4),
             Vb + (size_t)(cc * 8 + r + 4) * NPIX + n0cta + q * 4);
    };
    stageV(0, 0);
    CP_COMMIT();

    float acc[4][4][4];
#pragma unroll
    for (int mi = 0; mi < 4; mi++)
#pragma unroll
        for (int nj = 0; nj < 4; nj++)
#pragma unroll
            for (int e = 0; e < 4; e++) acc[mi][nj][e] = 0.f;

    for (int cc = 0; cc < 16; cc++) {
        if (cc < 15) {
            stageV((cc + 1) & 1, cc + 1);
            CP_COMMIT();
            CP_WAIT1();
        } else {
            CP_WAIT0();
        }
        __syncthreads();
        const float* sv = sVc + (cc & 1) * 8 * 264;
        uint4 af[4];
#pragma unroll
        for (int mi = 0; mi < 4; mi++) {
            int m0 = mi * 16;
            int c0 = cc * 8;
            af[mi].x = __float_as_uint(st2[(c0 + lr) * 72 + m0 + lq]);
            af[mi].y = __float_as_uint(st2[(c0 + lr) * 72 + m0 + lq + 8]);
            af[mi].z = __float_as_uint(st2[(c0 + lr + 4) * 72 + m0 + lq]);
            af[mi].w = __float_as_uint(st2[(c0 + lr + 4) * 72 + m0 + lq + 8]);
        }
#pragma unroll
        for (int nj = 0; nj < 4; nj++) {
            int n0 = wid * 32 + nj * 8;
            uint32_t b0 = __float_as_uint(sv[lr * 264 + n0 + lq]);
            uint32_t b1 = __float_as_uint(sv[(lr + 4) * 264 + n0 + lq]);
#pragma unroll
            for (int mi = 0; mi < 4; mi++) mma_tf32(acc[mi][nj], af[mi], b0, b1);
        }
        __syncthreads();
    }

#pragma unroll
    for (int mi = 0; mi < 4; mi++) {
        int m0 = mi * 16 + lq;
#pragma unroll
        for (int nj = 0; nj < 4; nj++) {
            int n = n0cta + wid * 32 + nj * 8 + lr * 2;
            *(float2*)(out + ((size_t)(b * 64 + m0)) * NPIX + n) =
                make_float2(acc[mi][nj][0], acc[mi][nj][1]);
            *(float2*)(out + ((size_t)(b * 64 + m0 + 8)) * NPIX + n) =
                make_float2(acc[mi][nj][2], acc[mi][nj][3]);
        }
    }
}

// ---------------- launch -----------------------------------------------------
extern "C" void kernel_launch(void* const* d_in, const int* in_sizes, int n_in,
                              void* d_out, int out_size)
{
    const float* x1 = (const float*)d_in[0];
    const float* x2 = (const float*)d_in[1];
    const float* w1 = (const float*)d_in[2];
    const float* b1 = (const float*)d_in[3];
    const float* w2 = (const float*)d_in[4];
    const float* b2 = (const float*)d_in[5];
    const float* wi = (const float*)d_in[6];
    const float* bi = (const float*)d_in[7];
    float* out = (float*)d_out;

    static bool attr_done = false;
    if (!attr_done) {
        cudaFuncSetAttribute(solve_kernel, cudaFuncAttributeMaxDynamicSharedMemorySize,
                             128 * 192 * sizeof(float));
        cudaFuncSetAttribute(conv_mma_kernel<true>,
                             cudaFuncAttributeMaxDynamicSharedMemorySize, CONV_SMEM);
        cudaFuncSetAttribute(conv_mma_kernel<false>,
                             cudaFuncAttributeMaxDynamicSharedMemorySize, CONV_SMEM);
        cudaFuncSetAttribute(proj_mma_kernel,
                             cudaFuncAttributeMaxDynamicSharedMemorySize, PROJ_SMEM);
        attr_done = true;
    }

    uint32_t* wr1;  cudaGetSymbolAddress((void**)&wr1, g_wr1);
    uint32_t* wr2;  cudaGetSymbolAddress((void**)&wr2, g_wr2);
    uint32_t* wir;  cudaGetSymbolAddress((void**)&wir, g_wir);

    prep_cat_kernel<<<8192, 256>>>(x1, x2);
    repack_all_kernel<<<304, 256>>>(w1, w2, wi, wr1, wr2, wir);

    dim3 cgrid(8, 16, 4);
    conv_mma_kernel<true><<<cgrid, 256, CONV_SMEM>>>(b1);
    gemm1x1_kernel<<<dim3(128, 4), 256>>>(bi);
    conv_mma_kernel<false><<<cgrid, 256, CONV_SMEM>>>(b2);

    rowsum_scale_kernel<<<512, 256>>>();
    gemmG_mma_kernel<<<dim3(NSLICE, BATCH), 256>>>();
    reduceG_kernel<<<256, 256>>>();
    gemmT_mma_kernel<<<dim3(NSLICE, BATCH), 256>>>();
    solve_kernel<<<BATCH, 768, 128 * 192 * sizeof(float)>>>();
    proj_mma_kernel<<<dim3(64, BATCH), 256, PROJ_SMEM>>>(out);
}